// round 1
// baseline (speedup 1.0000x reference)
#include <cuda_runtime.h>
#include <math.h>

#define BATCH 4
#define NSEQ  4096
#define CDIM  128

#define BM 128           // query rows per block
#define BN 64            // key rows per tile
#define KSTRIDE 132      // padded smem row stride (floats) for Q/K/V tiles
#define PSTRIDE 68       // padded smem row stride for P tile

// Scratch for Q, K, V projections (8 MB each). Device globals: allocation-free.
__device__ float g_Q[BATCH * NSEQ * CDIM];
__device__ float g_K[BATCH * NSEQ * CDIM];
__device__ float g_V[BATCH * NSEQ * CDIM];

// ---------------------------------------------------------------------------
// Kernel 1: QKV projection.  out[row, d] = sum_c x[row, c] * W[c, d] + b[d]
// grid = (B*N/64, 3), block = 256. blockIdx.y selects q/k/v.
// ---------------------------------------------------------------------------
__global__ void __launch_bounds__(256) qkv_proj_kernel(
    const float* __restrict__ x,
    const float* __restrict__ wq, const float* __restrict__ bq,
    const float* __restrict__ wk, const float* __restrict__ bk,
    const float* __restrict__ wv, const float* __restrict__ bv)
{
    __shared__ float Xs[64 * 128];   // X tile, broadcast reads -> no pad needed
    __shared__ float Ws[16 * 128];   // W chunk

    const int which = blockIdx.y;
    const float* w    = (which == 0) ? wq : ((which == 1) ? wk : wv);
    const float* bias = (which == 0) ? bq : ((which == 1) ? bk : bv);
    float* outg       = (which == 0) ? g_Q : ((which == 1) ? g_K : g_V);

    const int row0 = blockIdx.x * 64;
    const int tid  = threadIdx.x;
    const int ty   = tid >> 4;   // 0..15 -> rows ty*4 .. ty*4+3
    const int tx   = tid & 15;   // 0..15 -> cols tx*8 .. tx*8+7

    // Load X tile (64 x 128 floats = 2048 float4), 8 per thread.
    {
        const float4* xg4 = (const float4*)(x + (size_t)row0 * CDIM);
        float4* Xs4 = (float4*)Xs;
        #pragma unroll
        for (int i = 0; i < 8; i++)
            Xs4[tid + i * 256] = xg4[tid + i * 256];
    }

    float acc[4][8];
    #pragma unroll
    for (int i = 0; i < 4; i++)
        #pragma unroll
        for (int j = 0; j < 8; j++)
            acc[i][j] = 0.0f;

    for (int kc = 0; kc < 8; kc++) {
        __syncthreads();   // kc=0: covers Xs load; else: previous chunk consumed
        // Load W chunk [16 x 128] = 512 float4, 2 per thread.
        {
            const float4* wg4 = (const float4*)(w + (size_t)(kc * 16) * CDIM);
            float4* Ws4 = (float4*)Ws;
            Ws4[tid]       = wg4[tid];
            Ws4[tid + 256] = wg4[tid + 256];
        }
        __syncthreads();

        #pragma unroll
        for (int k = 0; k < 16; k++) {
            float xr[4];
            #pragma unroll
            for (int i = 0; i < 4; i++)
                xr[i] = Xs[(ty * 4 + i) * 128 + kc * 16 + k];
            const float4 w0 = *(const float4*)&Ws[k * 128 + tx * 8];
            const float4 w1 = *(const float4*)&Ws[k * 128 + tx * 8 + 4];
            #pragma unroll
            for (int i = 0; i < 4; i++) {
                acc[i][0] = fmaf(xr[i], w0.x, acc[i][0]);
                acc[i][1] = fmaf(xr[i], w0.y, acc[i][1]);
                acc[i][2] = fmaf(xr[i], w0.z, acc[i][2]);
                acc[i][3] = fmaf(xr[i], w0.w, acc[i][3]);
                acc[i][4] = fmaf(xr[i], w1.x, acc[i][4]);
                acc[i][5] = fmaf(xr[i], w1.y, acc[i][5]);
                acc[i][6] = fmaf(xr[i], w1.z, acc[i][6]);
                acc[i][7] = fmaf(xr[i], w1.w, acc[i][7]);
            }
        }
    }

    // Bias + store.
    float b0[8];
    #pragma unroll
    for (int j = 0; j < 8; j++) b0[j] = bias[tx * 8 + j];

    #pragma unroll
    for (int i = 0; i < 4; i++) {
        float4 o0, o1;
        o0.x = acc[i][0] + b0[0];  o0.y = acc[i][1] + b0[1];
        o0.z = acc[i][2] + b0[2];  o0.w = acc[i][3] + b0[3];
        o1.x = acc[i][4] + b0[4];  o1.y = acc[i][5] + b0[5];
        o1.z = acc[i][6] + b0[6];  o1.w = acc[i][7] + b0[7];
        float* orow = outg + (size_t)(row0 + ty * 4 + i) * CDIM + tx * 8;
        *(float4*)orow       = o0;
        *(float4*)(orow + 4) = o1;
    }
}

// ---------------------------------------------------------------------------
// Kernel 2: flash attention (fp32, online softmax).
// grid = (N/BM, B), block = 512.
// Thread layout: ty = tid>>4 (0..31) owns S/O rows ty*4..ty*4+3,
//                tx = tid&15 owns S cols {j*16+tx} and O cols tx*8..tx*8+7.
// ---------------------------------------------------------------------------
__global__ void __launch_bounds__(512, 1) attn_kernel(float* __restrict__ out)
{
    extern __shared__ float sm[];
    float* Qs = sm;                          // BM * KSTRIDE
    float* Ks = Qs + BM * KSTRIDE;           // BN * KSTRIDE
    float* Vs = Ks + BN * KSTRIDE;           // BN * KSTRIDE
    float* Ps = Vs + BN * KSTRIDE;           // BM * PSTRIDE

    const int b   = blockIdx.y;
    const int q0  = blockIdx.x * BM;
    const int tid = threadIdx.x;
    const int ty  = tid >> 4;   // 0..31
    const int tx  = tid & 15;   // 0..15

    // Load Q tile (128 x 128 = 4096 float4), 8 per thread.
    {
        const float* Qg = g_Q + (size_t)(b * NSEQ + q0) * CDIM;
        #pragma unroll
        for (int i = 0; i < 8; i++) {
            int idx = tid + i * 512;          // float4 index
            int r   = idx >> 5;               // 32 float4 per row
            int c4  = idx & 31;
            *(float4*)&Qs[r * KSTRIDE + c4 * 4] =
                *(const float4*)&Qg[r * CDIM + c4 * 4];
        }
    }

    float m_run[4], l_run[4], O[4][8];
    #pragma unroll
    for (int i = 0; i < 4; i++) {
        m_run[i] = -1e30f;
        l_run[i] = 0.0f;
        #pragma unroll
        for (int j = 0; j < 8; j++) O[i][j] = 0.0f;
    }

    const float scale = 0.08838834764831845f;  // 1/sqrt(128)

    for (int kt = 0; kt < NSEQ / BN; kt++) {
        __syncthreads();   // everyone done with previous K/V/P before reload

        // Load K, V tiles (64 x 128 each = 2048 float4 each), 4+4 per thread.
        {
            const float* Kg = g_K + (size_t)(b * NSEQ + kt * BN) * CDIM;
            const float* Vg = g_V + (size_t)(b * NSEQ + kt * BN) * CDIM;
            #pragma unroll
            for (int i = 0; i < 4; i++) {
                int idx = tid + i * 512;
                int r   = idx >> 5;
                int c4  = idx & 31;
                *(float4*)&Ks[r * KSTRIDE + c4 * 4] =
                    *(const float4*)&Kg[r * CDIM + c4 * 4];
                *(float4*)&Vs[r * KSTRIDE + c4 * 4] =
                    *(const float4*)&Vg[r * CDIM + c4 * 4];
            }
        }
        __syncthreads();

        // S[i][j] = Q[row ty*4+i] . K[col j*16+tx]
        float S[4][4];
        #pragma unroll
        for (int i = 0; i < 4; i++)
            #pragma unroll
            for (int j = 0; j < 4; j++) S[i][j] = 0.0f;

        #pragma unroll 4
        for (int d = 0; d < CDIM; d += 4) {
            float4 q[4], k4[4];
            #pragma unroll
            for (int i = 0; i < 4; i++)
                q[i] = *(const float4*)&Qs[(ty * 4 + i) * KSTRIDE + d];
            #pragma unroll
            for (int j = 0; j < 4; j++)
                k4[j] = *(const float4*)&Ks[(j * 16 + tx) * KSTRIDE + d];
            #pragma unroll
            for (int i = 0; i < 4; i++) {
                #pragma unroll
                for (int j = 0; j < 4; j++) {
                    S[i][j] = fmaf(q[i].x, k4[j].x, S[i][j]);
                    S[i][j] = fmaf(q[i].y, k4[j].y, S[i][j]);
                    S[i][j] = fmaf(q[i].z, k4[j].z, S[i][j]);
                    S[i][j] = fmaf(q[i].w, k4[j].w, S[i][j]);
                }
            }
        }

        // Online softmax update for the 4 owned rows.
        #pragma unroll
        for (int i = 0; i < 4; i++) {
            #pragma unroll
            for (int j = 0; j < 4; j++) S[i][j] *= scale;

            float mx = S[i][0];
            mx = fmaxf(mx, S[i][1]);
            mx = fmaxf(mx, S[i][2]);
            mx = fmaxf(mx, S[i][3]);
            #pragma unroll
            for (int off = 8; off > 0; off >>= 1)
                mx = fmaxf(mx, __shfl_xor_sync(0xffffffffu, mx, off));

            const float mnew  = fmaxf(m_run[i], mx);
            const float alpha = __expf(m_run[i] - mnew);
            m_run[i] = mnew;

            float rs = 0.0f;
            #pragma unroll
            for (int j = 0; j < 4; j++) {
                float p = __expf(S[i][j] - mnew);
                S[i][j] = p;
                rs += p;
            }
            #pragma unroll
            for (int off = 8; off > 0; off >>= 1)
                rs += __shfl_xor_sync(0xffffffffu, rs, off);

            l_run[i] = l_run[i] * alpha + rs;

            #pragma unroll
            for (int j = 0; j < 8; j++) O[i][j] *= alpha;

            // Scatter P row fragment (cols j*16+tx).
            #pragma unroll
            for (int j = 0; j < 4; j++)
                Ps[(ty * 4 + i) * PSTRIDE + j * 16 + tx] = S[i][j];
        }
        __syncthreads();

        // O += P @ V
        #pragma unroll 4
        for (int m = 0; m < BN; m++) {
            const float4 v0 = *(const float4*)&Vs[m * KSTRIDE + tx * 8];
            const float4 v1 = *(const float4*)&Vs[m * KSTRIDE + tx * 8 + 4];
            #pragma unroll
            for (int i = 0; i < 4; i++) {
                const float p = Ps[(ty * 4 + i) * PSTRIDE + m];
                O[i][0] = fmaf(p, v0.x, O[i][0]);
                O[i][1] = fmaf(p, v0.y, O[i][1]);
                O[i][2] = fmaf(p, v0.z, O[i][2]);
                O[i][3] = fmaf(p, v0.w, O[i][3]);
                O[i][4] = fmaf(p, v1.x, O[i][4]);
                O[i][5] = fmaf(p, v1.y, O[i][5]);
                O[i][6] = fmaf(p, v1.z, O[i][6]);
                O[i][7] = fmaf(p, v1.w, O[i][7]);
            }
        }
    }

    // Epilogue: normalize and store.
    float* Og = out + (size_t)(b * NSEQ + q0) * CDIM;
    #pragma unroll
    for (int i = 0; i < 4; i++) {
        const float inv = 1.0f / l_run[i];
        float4 o0, o1;
        o0.x = O[i][0] * inv;  o0.y = O[i][1] * inv;
        o0.z = O[i][2] * inv;  o0.w = O[i][3] * inv;
        o1.x = O[i][4] * inv;  o1.y = O[i][5] * inv;
        o1.z = O[i][6] * inv;  o1.w = O[i][7] * inv;
        float* orow = Og + (size_t)(ty * 4 + i) * CDIM + tx * 8;
        *(float4*)orow       = o0;
        *(float4*)(orow + 4) = o1;
    }
}

// ---------------------------------------------------------------------------
// Launch
// ---------------------------------------------------------------------------
extern "C" void kernel_launch(void* const* d_in, const int* in_sizes, int n_in,
                              void* d_out, int out_size)
{
    const float* x  = (const float*)d_in[0];
    const float* wq = (const float*)d_in[1];
    const float* bq = (const float*)d_in[2];
    const float* wk = (const float*)d_in[3];
    const float* bk = (const float*)d_in[4];
    const float* wv = (const float*)d_in[5];
    const float* bv = (const float*)d_in[6];
    float* out = (float*)d_out;

    // QKV projection: 256 row-tiles x 3 matrices.
    dim3 g1(BATCH * NSEQ / 64, 3);
    qkv_proj_kernel<<<g1, 256>>>(x, wq, bq, wk, bk, wv, bv);

    // Flash attention.
    const size_t smem_bytes =
        (size_t)(BM * KSTRIDE + 2 * BN * KSTRIDE + BM * PSTRIDE) * sizeof(float);
    cudaFuncSetAttribute(attn_kernel,
                         cudaFuncAttributeMaxDynamicSharedMemorySize,
                         (int)smem_bytes);
    dim3 g2(NSEQ / BM, BATCH);
    attn_kernel<<<g2, 512, smem_bytes>>>(out);
}

// round 3
// speedup vs baseline: 3.5481x; 3.5481x over previous
#include <cuda_runtime.h>
#include <cuda_fp16.h>
#include <cstdint>
#include <math.h>

#define BATCH 4
#define NSEQ  4096
#define CDIM  128
#define BM    128
#define BN    64
#define NKT   (NSEQ / BN)                  // 64 key tiles
#define ATTN_SCALE 0.08838834764831845f    // 1/sqrt(128)

// ---------------------------------------------------------------------------
// Global scratch: fp16 hi/lo split Q, K, V, all [b*N + n][c] row-major.
// ---------------------------------------------------------------------------
__device__ __half g_Qh[BATCH * NSEQ * CDIM];
__device__ __half g_Ql[BATCH * NSEQ * CDIM];
__device__ __half g_Kh[BATCH * NSEQ * CDIM];
__device__ __half g_Kl[BATCH * NSEQ * CDIM];
__device__ __half g_Vh[BATCH * NSEQ * CDIM];
__device__ __half g_Vl[BATCH * NSEQ * CDIM];

// ---------------------------------------------------------------------------
// PTX helpers (baseline sm_80+ features only: ldmatrix, mma.sync, cp.async)
// ---------------------------------------------------------------------------
__device__ __forceinline__ uint32_t smem_u32(const void* p) {
    uint32_t a;
    asm("{ .reg .u64 t; cvta.to.shared.u64 t, %1; cvt.u32.u64 %0, t; }"
        : "=r"(a) : "l"(p));
    return a;
}
__device__ __forceinline__ uint64_t gaddr(const void* p) {
    uint64_t r;
    asm("cvta.to.global.u64 %0, %1;" : "=l"(r) : "l"(p));
    return r;
}

#define LDSM_X4(R, a) \
    asm volatile("ldmatrix.sync.aligned.m8n8.x4.shared.b16 {%0,%1,%2,%3}, [%4];" \
        : "=r"((R)[0]), "=r"((R)[1]), "=r"((R)[2]), "=r"((R)[3]) : "r"(a))
#define LDSM_X4T(R, a) \
    asm volatile("ldmatrix.sync.aligned.m8n8.x4.trans.shared.b16 {%0,%1,%2,%3}, [%4];" \
        : "=r"((R)[0]), "=r"((R)[1]), "=r"((R)[2]), "=r"((R)[3]) : "r"(a))

#define MMA16816(D, A, B0, B1) \
    asm volatile("mma.sync.aligned.m16n8k16.row.col.f32.f16.f16.f32 " \
        "{%0,%1,%2,%3}, {%4,%5,%6,%7}, {%8,%9}, {%0,%1,%2,%3};" \
        : "+f"((D)[0]), "+f"((D)[1]), "+f"((D)[2]), "+f"((D)[3]) \
        : "r"((A)[0]), "r"((A)[1]), "r"((A)[2]), "r"((A)[3]), "r"(B0), "r"(B1))

#define CP16(dst, src) \
    asm volatile("cp.async.cg.shared.global [%0], [%1], 16;" \
        :: "r"(dst), "l"(src) : "memory")
#define CP_COMMIT() asm volatile("cp.async.commit_group;" ::: "memory")
#define CP_WAIT1()  asm volatile("cp.async.wait_group 1;" ::: "memory")
#define CP_WAIT0()  asm volatile("cp.async.wait_group 0;" ::: "memory")

// Split fp32 pair -> packed fp16 hi / fp16 lo
__device__ __forceinline__ void split2(float x, float y,
                                       uint32_t& hi, uint32_t& lo) {
    __half hx = __float2half_rn(x), hy = __float2half_rn(y);
    __half2 h2 = __halves2half2(hx, hy);
    __half2 l2 = __floats2half2_rn(x - __half2float(hx), y - __half2float(hy));
    hi = *(uint32_t*)&h2;
    lo = *(uint32_t*)&l2;
}

// ---------------------------------------------------------------------------
// Kernel 1: QKV projection (SIMT fp32 GEMM) -> fp16 hi/lo split outputs.
// grid = (B*N/64, 3), block = 256.
// ---------------------------------------------------------------------------
__global__ void __launch_bounds__(256) qkv_proj_kernel(
    const float* __restrict__ x,
    const float* __restrict__ wq, const float* __restrict__ bq,
    const float* __restrict__ wk, const float* __restrict__ bk,
    const float* __restrict__ wv, const float* __restrict__ bv)
{
    __shared__ float Xs[64 * 128];
    __shared__ float Ws[16 * 128];

    const int which = blockIdx.y;
    const float* w    = (which == 0) ? wq : ((which == 1) ? wk : wv);
    const float* bias = (which == 0) ? bq : ((which == 1) ? bk : bv);
    __half* gh = (which == 0) ? g_Qh : ((which == 1) ? g_Kh : g_Vh);
    __half* gl = (which == 0) ? g_Ql : ((which == 1) ? g_Kl : g_Vl);

    const int row0 = blockIdx.x * 64;
    const int tid  = threadIdx.x;
    const int ty   = tid >> 4;
    const int tx   = tid & 15;

    {
        const float4* xg4 = (const float4*)(x + (size_t)row0 * CDIM);
        float4* Xs4 = (float4*)Xs;
        #pragma unroll
        for (int i = 0; i < 8; i++)
            Xs4[tid + i * 256] = xg4[tid + i * 256];
    }

    float acc[4][8];
    #pragma unroll
    for (int i = 0; i < 4; i++)
        #pragma unroll
        for (int j = 0; j < 8; j++) acc[i][j] = 0.0f;

    for (int kc = 0; kc < 8; kc++) {
        __syncthreads();
        {
            const float4* wg4 = (const float4*)(w + (size_t)(kc * 16) * CDIM);
            float4* Ws4 = (float4*)Ws;
            Ws4[tid]       = wg4[tid];
            Ws4[tid + 256] = wg4[tid + 256];
        }
        __syncthreads();

        #pragma unroll
        for (int k = 0; k < 16; k++) {
            float xr[4];
            #pragma unroll
            for (int i = 0; i < 4; i++)
                xr[i] = Xs[(ty * 4 + i) * 128 + kc * 16 + k];
            const float4 w0 = *(const float4*)&Ws[k * 128 + tx * 8];
            const float4 w1 = *(const float4*)&Ws[k * 128 + tx * 8 + 4];
            #pragma unroll
            for (int i = 0; i < 4; i++) {
                acc[i][0] = fmaf(xr[i], w0.x, acc[i][0]);
                acc[i][1] = fmaf(xr[i], w0.y, acc[i][1]);
                acc[i][2] = fmaf(xr[i], w0.z, acc[i][2]);
                acc[i][3] = fmaf(xr[i], w0.w, acc[i][3]);
                acc[i][4] = fmaf(xr[i], w1.x, acc[i][4]);
                acc[i][5] = fmaf(xr[i], w1.y, acc[i][5]);
                acc[i][6] = fmaf(xr[i], w1.z, acc[i][6]);
                acc[i][7] = fmaf(xr[i], w1.w, acc[i][7]);
            }
        }
    }

    float b0[8];
    #pragma unroll
    for (int j = 0; j < 8; j++) b0[j] = bias[tx * 8 + j];

    #pragma unroll
    for (int i = 0; i < 4; i++) {
        const int row = row0 + ty * 4 + i;
        uint32_t hi[4], lo[4];
        #pragma unroll
        for (int j = 0; j < 4; j++)
            split2(acc[i][2 * j] + b0[2 * j], acc[i][2 * j + 1] + b0[2 * j + 1],
                   hi[j], lo[j]);
        uint32_t* ph = (uint32_t*)(gh + (size_t)row * CDIM + tx * 8);
        uint32_t* pl = (uint32_t*)(gl + (size_t)row * CDIM + tx * 8);
        #pragma unroll
        for (int j = 0; j < 4; j++) { ph[j] = hi[j]; pl[j] = lo[j]; }
    }
}

// ---------------------------------------------------------------------------
// Kernel 2: HMMA flash attention (fp16 split, 3-pass, no-max softmax).
// grid = (N/BM, B), block = 256 (8 warps, m16 stripe each).
// ---------------------------------------------------------------------------
// Dynamic smem (bytes):
//   Qh: 0      (128 rows x 256B, swizzled)     Ql: 32768
//   KV[2] @ 65536 + s*65536, each: Kh+0 Kl+16384 Vh+32768 Vl+49152
#define SM_KV  65536
#define SMEM_ATTN_BYTES (65536 + 2 * 65536)

__global__ void __launch_bounds__(256, 1) attn_kernel(float* __restrict__ out)
{
    extern __shared__ __align__(1024) char smem[];
    const uint32_t sbase = smem_u32(smem);

    const int b    = blockIdx.y;
    const int q0   = blockIdx.x * BM;
    const int tid  = threadIdx.x;
    const int lane = tid & 31;
    const int wrp  = tid >> 5;
    const int m0   = wrp * 16;

    const uint64_t gQh = gaddr(g_Qh) + ((size_t)(b * NSEQ + q0) * CDIM) * 2;
    const uint64_t gQl = gaddr(g_Ql) + ((size_t)(b * NSEQ + q0) * CDIM) * 2;
    const uint64_t gKh = gaddr(g_Kh) + ((size_t)(b * NSEQ) * CDIM) * 2;
    const uint64_t gKl = gaddr(g_Kl) + ((size_t)(b * NSEQ) * CDIM) * 2;
    const uint64_t gVh = gaddr(g_Vh) + ((size_t)(b * NSEQ) * CDIM) * 2;
    const uint64_t gVl = gaddr(g_Vl) + ((size_t)(b * NSEQ) * CDIM) * 2;

    // ---- stage Q (once): 2 arrays x 128 rows x 16 chunks of 16B ----
    {
        #pragma unroll
        for (int i = 0; i < 16; i++) {
            int idx = tid + i * 256;               // 0..4095
            int arr = idx >> 11;                   // 0=hi 1=lo
            int rem = idx & 2047;
            int r   = rem >> 4;
            int c   = rem & 15;
            uint32_t dst = sbase + arr * 32768 + r * 256 + ((c ^ (r & 7)) << 4);
            uint64_t src = (arr ? gQl : gQh) + ((size_t)r * CDIM + c * 8) * 2;
            CP16(dst, src);
        }
    }
    // ---- stage KV tile 0 into buffer 0 ----
    {
        #pragma unroll
        for (int i = 0; i < 16; i++) {
            int idx = tid + i * 256;               // 0..4095
            int arr = idx >> 10;                   // 0=Kh 1=Kl 2=Vh 3=Vl
            int rem = idx & 1023;
            int r   = rem >> 4;
            int c   = rem & 15;
            uint32_t dst = sbase + SM_KV + arr * 16384 + r * 256
                         + ((c ^ (r & 7)) << 4);
            uint64_t base = (arr == 0) ? gKh : (arr == 1) ? gKl
                          : (arr == 2) ? gVh : gVl;
            uint64_t src = base + ((size_t)r * CDIM + c * 8) * 2;
            CP16(dst, src);
        }
    }
    CP_COMMIT();

    float O[16][4];
    #pragma unroll
    for (int t = 0; t < 16; t++)
        #pragma unroll
        for (int j = 0; j < 4; j++) O[t][j] = 0.0f;
    float l0 = 0.0f, l1 = 0.0f;

    // Per-lane ldmatrix row/col selectors.
    const int ln7   = lane & 7;
    const int selA  = (lane >> 3) & 1;    // Q: +8 row     K/V: chunk/+8-row alt
    const int selB  = (lane >> 4) & 1;

    const int qrow  = m0 + ln7 + selA * 8;
    const uint32_t qbh = sbase + qrow * 256;
    const int qswz  = qrow & 7;

    for (int kt = 0; kt < NKT; kt++) {
        const int s = kt & 1;
        const uint32_t kvb = sbase + SM_KV + s * 65536;

        if (kt + 1 < NKT) {
            const uint32_t kvn = sbase + SM_KV + (s ^ 1) * 65536;
            const size_t rowoff = (size_t)(kt + 1) * BN;
            #pragma unroll
            for (int i = 0; i < 16; i++) {
                int idx = tid + i * 256;
                int arr = idx >> 10;
                int rem = idx & 1023;
                int r   = rem >> 4;
                int c   = rem & 15;
                uint32_t dst = kvn + arr * 16384 + r * 256 + ((c ^ (r & 7)) << 4);
                uint64_t base = (arr == 0) ? gKh : (arr == 1) ? gKl
                              : (arr == 2) ? gVh : gVl;
                uint64_t src = base + ((rowoff + r) * CDIM + c * 8) * 2;
                CP16(dst, src);
            }
            CP_COMMIT();
            CP_WAIT1();
        } else {
            CP_WAIT0();
        }
        __syncthreads();

        // ================= S = Q K^T (3-pass split) =================
        float S[8][4];
        #pragma unroll
        for (int t = 0; t < 8; t++)
            #pragma unroll
            for (int j = 0; j < 4; j++) S[t][j] = 0.0f;

        #pragma unroll
        for (int ks = 0; ks < 8; ks++) {
            const int qc = 2 * ks + selB;
            const uint32_t qa = qbh + ((qc ^ qswz) << 4);
            uint32_t qh[4], ql[4];
            LDSM_X4(qh, qa);
            LDSM_X4(ql, qa + 32768);

            #pragma unroll
            for (int p = 0; p < 4; p++) {
                const int kr = p * 16 + selB * 8 + ln7;
                const int kc = 2 * ks + selA;
                const uint32_t ka = kvb + kr * 256 + ((kc ^ (kr & 7)) << 4);
                uint32_t bh[4], bl[4];
                LDSM_X4(bh, ka);
                LDSM_X4(bl, ka + 16384);
                MMA16816(S[2 * p],     qh, bh[0], bh[1]);
                MMA16816(S[2 * p],     qh, bl[0], bl[1]);
                MMA16816(S[2 * p],     ql, bh[0], bh[1]);
                MMA16816(S[2 * p + 1], qh, bh[2], bh[3]);
                MMA16816(S[2 * p + 1], qh, bl[2], bl[3]);
                MMA16816(S[2 * p + 1], ql, bh[2], bh[3]);
            }
        }

        // ================= softmax (no max) =================
        float rs0 = 0.0f, rs1 = 0.0f;
        #pragma unroll
        for (int t = 0; t < 8; t++) {
            #pragma unroll
            for (int j = 0; j < 4; j++) {
                const float p = __expf(S[t][j] * ATTN_SCALE);
                S[t][j] = p;
                if (j < 2) rs0 += p; else rs1 += p;
            }
        }
        l0 += rs0;
        l1 += rs1;

        // ================= O += P V (3-pass split) =================
        #pragma unroll
        for (int kv = 0; kv < 4; kv++) {
            uint32_t ah[4], al[4];
            split2(S[2 * kv][0],     S[2 * kv][1],     ah[0], al[0]);
            split2(S[2 * kv][2],     S[2 * kv][3],     ah[1], al[1]);
            split2(S[2 * kv + 1][0], S[2 * kv + 1][1], ah[2], al[2]);
            split2(S[2 * kv + 1][2], S[2 * kv + 1][3], ah[3], al[3]);

            const int vrow = kv * 16 + selA * 8 + ln7;
            const uint32_t vb = kvb + 32768 + vrow * 256;
            const int vswz = vrow & 7;

            #pragma unroll
            for (int dp = 0; dp < 8; dp++) {
                const int vc = 2 * dp + selB;
                const uint32_t va = vb + ((vc ^ vswz) << 4);
                uint32_t vh[4], vl[4];
                LDSM_X4T(vh, va);
                LDSM_X4T(vl, va + 16384);
                MMA16816(O[2 * dp],     ah, vh[0], vh[1]);
                MMA16816(O[2 * dp],     ah, vl[0], vl[1]);
                MMA16816(O[2 * dp],     al, vh[0], vh[1]);
                MMA16816(O[2 * dp + 1], ah, vh[2], vh[3]);
                MMA16816(O[2 * dp + 1], ah, vl[2], vl[3]);
                MMA16816(O[2 * dp + 1], al, vh[2], vh[3]);
            }
        }
        __syncthreads();
    }

    // ================= epilogue =================
    l0 += __shfl_xor_sync(0xffffffffu, l0, 1);
    l0 += __shfl_xor_sync(0xffffffffu, l0, 2);
    l1 += __shfl_xor_sync(0xffffffffu, l1, 1);
    l1 += __shfl_xor_sync(0xffffffffu, l1, 2);
    const float inv0 = 1.0f / l0;
    const float inv1 = 1.0f / l1;

    const int grow = b * NSEQ + q0 + m0 + (lane >> 2);
    float* o0 = out + (size_t)grow * CDIM;
    float* o1 = o0 + 8 * CDIM;
    const int cb = (lane & 3) * 2;

    #pragma unroll
    for (int t = 0; t < 16; t++) {
        float2 r0, r1;
        r0.x = O[t][0] * inv0;  r0.y = O[t][1] * inv0;
        r1.x = O[t][2] * inv1;  r1.y = O[t][3] * inv1;
        *(float2*)(o0 + t * 8 + cb) = r0;
        *(float2*)(o1 + t * 8 + cb) = r1;
    }
}

// ---------------------------------------------------------------------------
// Launch
// ---------------------------------------------------------------------------
extern "C" void kernel_launch(void* const* d_in, const int* in_sizes, int n_in,
                              void* d_out, int out_size)
{
    const float* x  = (const float*)d_in[0];
    const float* wq = (const float*)d_in[1];
    const float* bq = (const float*)d_in[2];
    const float* wk = (const float*)d_in[3];
    const float* bk = (const float*)d_in[4];
    const float* wv = (const float*)d_in[5];
    const float* bv = (const float*)d_in[6];
    float* out = (float*)d_out;

    dim3 g1(BATCH * NSEQ / 64, 3);
    qkv_proj_kernel<<<g1, 256>>>(x, wq, bq, wk, bk, wv, bv);

    cudaFuncSetAttribute(attn_kernel,
                         cudaFuncAttributeMaxDynamicSharedMemorySize,
                         SMEM_ATTN_BYTES);
    dim3 g2(NSEQ / BM, BATCH);
    attn_kernel<<<g2, 256, SMEM_ATTN_BYTES>>>(out);
}

// round 4
// speedup vs baseline: 5.7570x; 1.6226x over previous
#include <cuda_runtime.h>
#include <cuda_fp16.h>
#include <cstdint>
#include <math.h>

#define BATCH 4
#define NSEQ  4096
#define CDIM  128
#define BM    128
#define BN    64
#define NKT   (NSEQ / BN)                  // 64 key tiles
#define ATTN_SCALE 0.08838834764831845f    // 1/sqrt(128)

// ---------------------------------------------------------------------------
// Global scratch (device globals: allocation-free).
// ---------------------------------------------------------------------------
__device__ __half g_Xh[BATCH * NSEQ * CDIM];   // x split hi
__device__ __half g_Xl[BATCH * NSEQ * CDIM];   // x split lo
__device__ __half g_Wh[3 * CDIM * CDIM];       // wq,wk,wv split hi
__device__ __half g_Wl[3 * CDIM * CDIM];       // wq,wk,wv split lo
__device__ __half g_Qh[BATCH * NSEQ * CDIM];   // Q split hi
__device__ __half g_Ql[BATCH * NSEQ * CDIM];   // Q split lo
__device__ __half g_Kh[BATCH * NSEQ * CDIM];   // K rounded fp16
__device__ __half g_Vh[BATCH * NSEQ * CDIM];   // V rounded fp16

// ---------------------------------------------------------------------------
// PTX helpers (sm_80-baseline features only)
// ---------------------------------------------------------------------------
__device__ __forceinline__ uint32_t smem_u32(const void* p) {
    uint32_t a;
    asm("{ .reg .u64 t; cvta.to.shared.u64 t, %1; cvt.u32.u64 %0, t; }"
        : "=r"(a) : "l"(p));
    return a;
}
__device__ __forceinline__ uint64_t gaddr(const void* p) {
    uint64_t r;
    asm("cvta.to.global.u64 %0, %1;" : "=l"(r) : "l"(p));
    return r;
}

#define LDSM_X4(R, a) \
    asm volatile("ldmatrix.sync.aligned.m8n8.x4.shared.b16 {%0,%1,%2,%3}, [%4];" \
        : "=r"((R)[0]), "=r"((R)[1]), "=r"((R)[2]), "=r"((R)[3]) : "r"(a))
#define LDSM_X4T(R, a) \
    asm volatile("ldmatrix.sync.aligned.m8n8.x4.trans.shared.b16 {%0,%1,%2,%3}, [%4];" \
        : "=r"((R)[0]), "=r"((R)[1]), "=r"((R)[2]), "=r"((R)[3]) : "r"(a))

#define MMA16816(D, A, B0, B1) \
    asm volatile("mma.sync.aligned.m16n8k16.row.col.f32.f16.f16.f32 " \
        "{%0,%1,%2,%3}, {%4,%5,%6,%7}, {%8,%9}, {%0,%1,%2,%3};" \
        : "+f"((D)[0]), "+f"((D)[1]), "+f"((D)[2]), "+f"((D)[3]) \
        : "r"((A)[0]), "r"((A)[1]), "r"((A)[2]), "r"((A)[3]), "r"(B0), "r"(B1))

#define CP16(dst, src) \
    asm volatile("cp.async.cg.shared.global [%0], [%1], 16;" \
        :: "r"(dst), "l"(src) : "memory")
#define CP_COMMIT() asm volatile("cp.async.commit_group;" ::: "memory")
#define CP_WAIT1()  asm volatile("cp.async.wait_group 1;" ::: "memory")
#define CP_WAIT0()  asm volatile("cp.async.wait_group 0;" ::: "memory")

// Split fp32 pair -> packed fp16 hi / fp16 lo
__device__ __forceinline__ void split2(float x, float y,
                                       uint32_t& hi, uint32_t& lo) {
    __half hx = __float2half_rn(x), hy = __float2half_rn(y);
    __half2 h2 = __halves2half2(hx, hy);
    __half2 l2 = __floats2half2_rn(x - __half2float(hx), y - __half2float(hy));
    hi = *(uint32_t*)&h2;
    lo = *(uint32_t*)&l2;
}

// ---------------------------------------------------------------------------
// Kernel 0: convert x and weights to split fp16 (mem-bound).
// ---------------------------------------------------------------------------
__global__ void __launch_bounds__(256) conv_kernel(
    const float* __restrict__ x,
    const float* __restrict__ wq, const float* __restrict__ wk,
    const float* __restrict__ wv)
{
    const int gid    = blockIdx.x * blockDim.x + threadIdx.x;
    const int stride = gridDim.x * blockDim.x;

    uint32_t* Xh32 = (uint32_t*)g_Xh;
    uint32_t* Xl32 = (uint32_t*)g_Xl;
    const float4* x4 = (const float4*)x;
    for (int i = gid; i < BATCH * NSEQ * CDIM / 4; i += stride) {
        const float4 v = x4[i];
        uint32_t h0, l0, h1, l1;
        split2(v.x, v.y, h0, l0);
        split2(v.z, v.w, h1, l1);
        Xh32[2 * i]     = h0;  Xl32[2 * i]     = l0;
        Xh32[2 * i + 1] = h1;  Xl32[2 * i + 1] = l1;
    }

    uint32_t* Wh32 = (uint32_t*)g_Wh;
    uint32_t* Wl32 = (uint32_t*)g_Wl;
    for (int i = gid; i < 3 * CDIM * CDIM / 4; i += stride) {
        const int m = i / (CDIM * CDIM / 4);
        const int r = i % (CDIM * CDIM / 4);
        const float4* ws = (const float4*)((m == 0) ? wq : (m == 1) ? wk : wv);
        const float4 v = ws[r];
        uint32_t h0, l0, h1, l1;
        split2(v.x, v.y, h0, l0);
        split2(v.z, v.w, h1, l1);
        Wh32[2 * i]     = h0;  Wl32[2 * i]     = l0;
        Wh32[2 * i + 1] = h1;  Wl32[2 * i + 1] = l1;
    }
}

// ---------------------------------------------------------------------------
// Kernel 1: QKV projection via HMMA, 3-pass split (Xh*Wh + Xh*Wl + Xl*Wh).
// grid = 128 (row tiles of 128), block = 256 (8 warps x m16).
// smem: Xh @0 (32KB), Xl @32768, W double buffer @65536 (each 64KB: Wh+Wl).
// ---------------------------------------------------------------------------
#define SM_PROJ_W 65536
#define SMEM_PROJ_BYTES (65536 + 2 * 65536)

__global__ void __launch_bounds__(256, 1) qkv_proj_kernel(
    const float* __restrict__ bq, const float* __restrict__ bk,
    const float* __restrict__ bv)
{
    extern __shared__ __align__(1024) char smem[];
    const uint32_t sbase = smem_u32(smem);

    const int tid  = threadIdx.x;
    const int lane = tid & 31;
    const int wrp  = tid >> 5;
    const int m0   = wrp * 16;
    const int r0   = blockIdx.x * 128;

    const uint64_t gXh = gaddr(g_Xh) + (size_t)r0 * CDIM * 2;
    const uint64_t gXl = gaddr(g_Xl) + (size_t)r0 * CDIM * 2;
    const uint64_t gWh = gaddr(g_Wh);
    const uint64_t gWl = gaddr(g_Wl);

    // Stage X (hi+lo) + W0 into buffer 0.
    #pragma unroll
    for (int i = 0; i < 16; i++) {
        int idx = tid + i * 256;               // 0..4095
        int arr = idx >> 11;                   // 0=hi 1=lo
        int rem = idx & 2047;
        int r   = rem >> 4;
        int c   = rem & 15;
        uint32_t dst = sbase + arr * 32768 + r * 256 + ((c ^ (r & 7)) << 4);
        CP16(dst, (arr ? gXl : gXh) + ((size_t)r * CDIM + c * 8) * 2);
    }
    #pragma unroll
    for (int i = 0; i < 16; i++) {
        int idx = tid + i * 256;
        int arr = idx >> 11;
        int rem = idx & 2047;
        int r   = rem >> 4;
        int c   = rem & 15;
        uint32_t dst = sbase + SM_PROJ_W + arr * 32768 + r * 256
                     + ((c ^ (r & 7)) << 4);
        CP16(dst, (arr ? gWl : gWh) + ((size_t)r * CDIM + c * 8) * 2);
    }
    CP_COMMIT();

    const int ln7  = lane & 7;
    const int selA = (lane >> 3) & 1;
    const int selB = (lane >> 4) & 1;

    const int xrow = m0 + ln7 + selA * 8;
    const uint32_t xbh = sbase + xrow * 256;
    const int xswz = xrow & 7;

    for (int m = 0; m < 3; m++) {
        if (m > 0) __syncthreads();           // all warps done with prev buffer
        if (m < 2) {
            const uint32_t wbuf = sbase + SM_PROJ_W + ((m + 1) & 1) * 65536;
            #pragma unroll
            for (int i = 0; i < 16; i++) {
                int idx = tid + i * 256;
                int arr = idx >> 11;
                int rem = idx & 2047;
                int r   = rem >> 4;
                int c   = rem & 15;
                uint32_t dst = wbuf + arr * 32768 + r * 256
                             + ((c ^ (r & 7)) << 4);
                const size_t off = ((size_t)(m + 1) * CDIM * CDIM
                                  + (size_t)r * CDIM + c * 8) * 2;
                CP16(dst, (arr ? gWl : gWh) + off);
            }
            CP_COMMIT();
            CP_WAIT1();
        } else {
            CP_WAIT0();
        }
        __syncthreads();

        const uint32_t wb = sbase + SM_PROJ_W + (m & 1) * 65536;

        float O[16][4];
        #pragma unroll
        for (int t = 0; t < 16; t++)
            #pragma unroll
            for (int j = 0; j < 4; j++) O[t][j] = 0.0f;

        #pragma unroll
        for (int ks = 0; ks < 8; ks++) {
            const int xc = 2 * ks + selB;
            const uint32_t xa = xbh + ((xc ^ xswz) << 4);
            uint32_t xh[4], xl[4];
            LDSM_X4(xh, xa);
            LDSM_X4(xl, xa + 32768);

            const int wrow = ks * 16 + selA * 8 + ln7;
            const uint32_t wbr = wb + wrow * 256;
            const int wswz = wrow & 7;

            #pragma unroll
            for (int dp = 0; dp < 8; dp++) {
                const int wc = 2 * dp + selB;
                const uint32_t wa = wbr + ((wc ^ wswz) << 4);
                uint32_t wh[4], wl[4];
                LDSM_X4T(wh, wa);
                LDSM_X4T(wl, wa + 32768);
                MMA16816(O[2 * dp],     xh, wh[0], wh[1]);
                MMA16816(O[2 * dp],     xh, wl[0], wl[1]);
                MMA16816(O[2 * dp],     xl, wh[0], wh[1]);
                MMA16816(O[2 * dp + 1], xh, wh[2], wh[3]);
                MMA16816(O[2 * dp + 1], xh, wl[2], wl[3]);
                MMA16816(O[2 * dp + 1], xl, wh[2], wh[3]);
            }
        }

        // Epilogue: bias + store (Q: split hi/lo; K,V: fp16 rn)
        const float* bias = (m == 0) ? bq : ((m == 1) ? bk : bv);
        const int gr0 = r0 + m0 + (lane >> 2);
        #pragma unroll
        for (int t = 0; t < 16; t++) {
            const int c0 = (t >> 1) * 16 + (t & 1) * 8 + 2 * (lane & 3);
            const float b0 = bias[c0];
            const float b1 = bias[c0 + 1];
            const float y00 = O[t][0] + b0, y01 = O[t][1] + b1;
            const float y10 = O[t][2] + b0, y11 = O[t][3] + b1;
            if (m == 0) {
                uint32_t h, l;
                split2(y00, y01, h, l);
                *(uint32_t*)(g_Qh + (size_t)gr0 * CDIM + c0) = h;
                *(uint32_t*)(g_Ql + (size_t)gr0 * CDIM + c0) = l;
                split2(y10, y11, h, l);
                *(uint32_t*)(g_Qh + (size_t)(gr0 + 8) * CDIM + c0) = h;
                *(uint32_t*)(g_Ql + (size_t)(gr0 + 8) * CDIM + c0) = l;
            } else {
                __half* dst = (m == 1) ? g_Kh : g_Vh;
                __half2 p0 = __floats2half2_rn(y00, y01);
                __half2 p1 = __floats2half2_rn(y10, y11);
                *(__half2*)(dst + (size_t)gr0 * CDIM + c0)       = p0;
                *(__half2*)(dst + (size_t)(gr0 + 8) * CDIM + c0) = p1;
            }
        }
    }
}

// ---------------------------------------------------------------------------
// Kernel 2: HMMA flash attention.
//   S = (Qh+Ql) * Kh   (2-pass),   O = (Ph+Pl) * Vh   (2-pass)
// grid = (N/BM, B), block = 256 (8 warps x m16). No-max softmax.
// smem: Qh @0 (32KB), Ql @32768, KV dbuf @65536 (each 32KB: Kh+Vh).
// ---------------------------------------------------------------------------
#define SM_KV  65536
#define SMEM_ATTN_BYTES (65536 + 2 * 32768)

__global__ void __launch_bounds__(256, 1) attn_kernel(float* __restrict__ out)
{
    extern __shared__ __align__(1024) char smem[];
    const uint32_t sbase = smem_u32(smem);

    const int b    = blockIdx.y;
    const int q0   = blockIdx.x * BM;
    const int tid  = threadIdx.x;
    const int lane = tid & 31;
    const int wrp  = tid >> 5;
    const int m0   = wrp * 16;

    const uint64_t gQh = gaddr(g_Qh) + ((size_t)(b * NSEQ + q0) * CDIM) * 2;
    const uint64_t gQl = gaddr(g_Ql) + ((size_t)(b * NSEQ + q0) * CDIM) * 2;
    const uint64_t gKh = gaddr(g_Kh) + ((size_t)(b * NSEQ) * CDIM) * 2;
    const uint64_t gVh = gaddr(g_Vh) + ((size_t)(b * NSEQ) * CDIM) * 2;

    // ---- stage Q hi+lo (once) ----
    #pragma unroll
    for (int i = 0; i < 16; i++) {
        int idx = tid + i * 256;               // 0..4095
        int arr = idx >> 11;
        int rem = idx & 2047;
        int r   = rem >> 4;
        int c   = rem & 15;
        uint32_t dst = sbase + arr * 32768 + r * 256 + ((c ^ (r & 7)) << 4);
        CP16(dst, (arr ? gQl : gQh) + ((size_t)r * CDIM + c * 8) * 2);
    }
    // ---- stage KV tile 0 ----
    #pragma unroll
    for (int i = 0; i < 8; i++) {
        int idx = tid + i * 256;               // 0..2047
        int arr = idx >> 10;                   // 0=Kh 1=Vh
        int rem = idx & 1023;
        int r   = rem >> 4;
        int c   = rem & 15;
        uint32_t dst = sbase + SM_KV + arr * 16384 + r * 256
                     + ((c ^ (r & 7)) << 4);
        CP16(dst, (arr ? gVh : gKh) + ((size_t)r * CDIM + c * 8) * 2);
    }
    CP_COMMIT();
    CP_WAIT0();
    __syncthreads();

    const int ln7  = lane & 7;
    const int selA = (lane >> 3) & 1;
    const int selB = (lane >> 4) & 1;

    const int qrow = m0 + ln7 + selA * 8;
    const uint32_t qbh = sbase + qrow * 256;
    const int qswz = qrow & 7;

    // ---- hoist Q-hi fragments into registers for the whole loop ----
    uint32_t qh[8][4];
    #pragma unroll
    for (int ks = 0; ks < 8; ks++) {
        const uint32_t qa = qbh + (((2 * ks + selB) ^ qswz) << 4);
        LDSM_X4(qh[ks], qa);
    }

    float O[16][4];
    #pragma unroll
    for (int t = 0; t < 16; t++)
        #pragma unroll
        for (int j = 0; j < 4; j++) O[t][j] = 0.0f;
    float l0 = 0.0f, l1 = 0.0f;

    for (int kt = 0; kt < NKT; kt++) {
        const int s = kt & 1;
        const uint32_t kvb = sbase + SM_KV + s * 32768;

        if (kt + 1 < NKT) {
            const uint32_t kvn = sbase + SM_KV + (s ^ 1) * 32768;
            const size_t rowoff = (size_t)(kt + 1) * BN;
            #pragma unroll
            for (int i = 0; i < 8; i++) {
                int idx = tid + i * 256;
                int arr = idx >> 10;
                int rem = idx & 1023;
                int r   = rem >> 4;
                int c   = rem & 15;
                uint32_t dst = kvn + arr * 16384 + r * 256 + ((c ^ (r & 7)) << 4);
                CP16(dst, (arr ? gVh : gKh) + ((rowoff + r) * CDIM + c * 8) * 2);
            }
            CP_COMMIT();
            CP_WAIT1();
        } else {
            CP_WAIT0();
        }
        __syncthreads();

        // ================= S = Q K^T : (qh + ql) * kh =================
        float S[8][4];
        #pragma unroll
        for (int t = 0; t < 8; t++)
            #pragma unroll
            for (int j = 0; j < 4; j++) S[t][j] = 0.0f;

        #pragma unroll
        for (int ks = 0; ks < 8; ks++) {
            const uint32_t qa = qbh + (((2 * ks + selB) ^ qswz) << 4);
            uint32_t ql[4];
            LDSM_X4(ql, qa + 32768);

            #pragma unroll
            for (int p = 0; p < 4; p++) {
                const int kr = p * 16 + selB * 8 + ln7;
                const int kc = 2 * ks + selA;
                const uint32_t ka = kvb + kr * 256 + ((kc ^ (kr & 7)) << 4);
                uint32_t kh[4];
                LDSM_X4(kh, ka);
                MMA16816(S[2 * p],     qh[ks], kh[0], kh[1]);
                MMA16816(S[2 * p],     ql,     kh[0], kh[1]);
                MMA16816(S[2 * p + 1], qh[ks], kh[2], kh[3]);
                MMA16816(S[2 * p + 1], ql,     kh[2], kh[3]);
            }
        }

        // ================= softmax (no max) =================
        #pragma unroll
        for (int t = 0; t < 8; t++) {
            #pragma unroll
            for (int j = 0; j < 4; j++) {
                const float p = __expf(S[t][j] * ATTN_SCALE);
                S[t][j] = p;
                if (j < 2) l0 += p; else l1 += p;
            }
        }

        // ================= O += P V : (ph + pl) * vh =================
        #pragma unroll
        for (int kv = 0; kv < 4; kv++) {
            uint32_t ah[4], al[4];
            split2(S[2 * kv][0],     S[2 * kv][1],     ah[0], al[0]);
            split2(S[2 * kv][2],     S[2 * kv][3],     ah[1], al[1]);
            split2(S[2 * kv + 1][0], S[2 * kv + 1][1], ah[2], al[2]);
            split2(S[2 * kv + 1][2], S[2 * kv + 1][3], ah[3], al[3]);

            const int vrow = kv * 16 + selA * 8 + ln7;
            const uint32_t vb = kvb + 16384 + vrow * 256;
            const int vswz = vrow & 7;

            #pragma unroll
            for (int dp = 0; dp < 8; dp++) {
                const int vc = 2 * dp + selB;
                const uint32_t va = vb + ((vc ^ vswz) << 4);
                uint32_t vh[4];
                LDSM_X4T(vh, va);
                MMA16816(O[2 * dp],     ah, vh[0], vh[1]);
                MMA16816(O[2 * dp],     al, vh[0], vh[1]);
                MMA16816(O[2 * dp + 1], ah, vh[2], vh[3]);
                MMA16816(O[2 * dp + 1], al, vh[2], vh[3]);
            }
        }
        __syncthreads();
    }

    // ================= epilogue =================
    l0 += __shfl_xor_sync(0xffffffffu, l0, 1);
    l0 += __shfl_xor_sync(0xffffffffu, l0, 2);
    l1 += __shfl_xor_sync(0xffffffffu, l1, 1);
    l1 += __shfl_xor_sync(0xffffffffu, l1, 2);
    const float inv0 = 1.0f / l0;
    const float inv1 = 1.0f / l1;

    const int grow = b * NSEQ + q0 + m0 + (lane >> 2);
    float* o0 = out + (size_t)grow * CDIM;
    float* o1 = o0 + 8 * CDIM;
    const int cb = (lane & 3) * 2;

    #pragma unroll
    for (int t = 0; t < 16; t++) {
        float2 r0v, r1v;
        r0v.x = O[t][0] * inv0;  r0v.y = O[t][1] * inv0;
        r1v.x = O[t][2] * inv1;  r1v.y = O[t][3] * inv1;
        *(float2*)(o0 + t * 8 + cb) = r0v;
        *(float2*)(o1 + t * 8 + cb) = r1v;
    }
}

// ---------------------------------------------------------------------------
// Launch
// ---------------------------------------------------------------------------
extern "C" void kernel_launch(void* const* d_in, const int* in_sizes, int n_in,
                              void* d_out, int out_size)
{
    const float* x  = (const float*)d_in[0];
    const float* wq = (const float*)d_in[1];
    const float* bq = (const float*)d_in[2];
    const float* wk = (const float*)d_in[3];
    const float* bk = (const float*)d_in[4];
    const float* wv = (const float*)d_in[5];
    const float* bv = (const float*)d_in[6];
    float* out = (float*)d_out;

    conv_kernel<<<1024, 256>>>(x, wq, wk, wv);

    cudaFuncSetAttribute(qkv_proj_kernel,
                         cudaFuncAttributeMaxDynamicSharedMemorySize,
                         SMEM_PROJ_BYTES);
    qkv_proj_kernel<<<BATCH * NSEQ / 128, 256, SMEM_PROJ_BYTES>>>(bq, bk, bv);

    cudaFuncSetAttribute(attn_kernel,
                         cudaFuncAttributeMaxDynamicSharedMemorySize,
                         SMEM_ATTN_BYTES);
    dim3 g2(NSEQ / BM, BATCH);
    attn_kernel<<<g2, 256, SMEM_ATTN_BYTES>>>(out);
}

// round 7
// speedup vs baseline: 7.1838x; 1.2478x over previous
#include <cuda_runtime.h>
#include <cuda_fp16.h>
#include <cstdint>
#include <math.h>

#define BATCH 4
#define NSEQ  4096
#define CDIM  128
#define BM    128
#define BN    64
#define NKT   (NSEQ / BN)                  // 64 key tiles
// 1/sqrt(128) * log2(e)  (fold softmax scale into exp2)
#define EXP2_SCALE 0.12752465736070462f

// ---------------------------------------------------------------------------
// Global scratch (device globals: allocation-free).
// ---------------------------------------------------------------------------
__device__ __half g_Xh[BATCH * NSEQ * CDIM];   // x split hi
__device__ __half g_Xl[BATCH * NSEQ * CDIM];   // x split lo
__device__ __half g_Wh[3 * CDIM * CDIM];       // wq,wk,wv split hi
__device__ __half g_Wl[3 * CDIM * CDIM];       // wq,wk,wv split lo
__device__ __half g_Qh[BATCH * NSEQ * CDIM];   // Q split hi
__device__ __half g_Ql[BATCH * NSEQ * CDIM];   // Q split lo
__device__ __half g_Kh[BATCH * NSEQ * CDIM];   // K rounded fp16
__device__ __half g_Vh[BATCH * NSEQ * CDIM];   // V rounded fp16

// ---------------------------------------------------------------------------
// PTX helpers (sm_80-baseline features only)
// ---------------------------------------------------------------------------
__device__ __forceinline__ uint32_t smem_u32(const void* p) {
    uint32_t a;
    asm("{ .reg .u64 t; cvta.to.shared.u64 t, %1; cvt.u32.u64 %0, t; }"
        : "=r"(a) : "l"(p));
    return a;
}
__device__ __forceinline__ uint64_t gaddr(const void* p) {
    uint64_t r;
    asm("cvta.to.global.u64 %0, %1;" : "=l"(r) : "l"(p));
    return r;
}

#define LDSM_X4(R, a) \
    asm volatile("ldmatrix.sync.aligned.m8n8.x4.shared.b16 {%0,%1,%2,%3}, [%4];" \
        : "=r"((R)[0]), "=r"((R)[1]), "=r"((R)[2]), "=r"((R)[3]) : "r"(a))
#define LDSM_X4T(R, a) \
    asm volatile("ldmatrix.sync.aligned.m8n8.x4.trans.shared.b16 {%0,%1,%2,%3}, [%4];" \
        : "=r"((R)[0]), "=r"((R)[1]), "=r"((R)[2]), "=r"((R)[3]) : "r"(a))

#define MMA16816(D, A, B0, B1) \
    asm volatile("mma.sync.aligned.m16n8k16.row.col.f32.f16.f16.f32 " \
        "{%0,%1,%2,%3}, {%4,%5,%6,%7}, {%8,%9}, {%0,%1,%2,%3};" \
        : "+f"((D)[0]), "+f"((D)[1]), "+f"((D)[2]), "+f"((D)[3]) \
        : "r"((A)[0]), "r"((A)[1]), "r"((A)[2]), "r"((A)[3]), "r"(B0), "r"(B1))

#define CP16(dst, src) \
    asm volatile("cp.async.cg.shared.global [%0], [%1], 16;" \
        :: "r"(dst), "l"(src) : "memory")
#define CP_COMMIT() asm volatile("cp.async.commit_group;" ::: "memory")
#define CP_WAIT1()  asm volatile("cp.async.wait_group 1;" ::: "memory")
#define CP_WAIT0()  asm volatile("cp.async.wait_group 0;" ::: "memory")

// Split fp32 pair -> packed fp16 hi / fp16 lo
__device__ __forceinline__ void split2(float x, float y,
                                       uint32_t& hi, uint32_t& lo) {
    __half hx = __float2half_rn(x), hy = __float2half_rn(y);
    __half2 h2 = __halves2half2(hx, hy);
    __half2 l2 = __floats2half2_rn(x - __half2float(hx), y - __half2float(hy));
    hi = *(uint32_t*)&h2;
    lo = *(uint32_t*)&l2;
}
// Round fp32 pair -> packed fp16 (hi only)
__device__ __forceinline__ uint32_t pack2(float x, float y) {
    __half2 h2 = __floats2half2_rn(x, y);
    return *(uint32_t*)&h2;
}

// ---------------------------------------------------------------------------
// Kernel 0: convert x and weights to split fp16 (mem-bound).
// ---------------------------------------------------------------------------
__global__ void __launch_bounds__(256) conv_kernel(
    const float* __restrict__ x,
    const float* __restrict__ wq, const float* __restrict__ wk,
    const float* __restrict__ wv)
{
    const int gid    = blockIdx.x * blockDim.x + threadIdx.x;
    const int stride = gridDim.x * blockDim.x;

    uint32_t* Xh32 = (uint32_t*)g_Xh;
    uint32_t* Xl32 = (uint32_t*)g_Xl;
    const float4* x4 = (const float4*)x;
    for (int i = gid; i < BATCH * NSEQ * CDIM / 4; i += stride) {
        const float4 v = x4[i];
        uint32_t h0, l0, h1, l1;
        split2(v.x, v.y, h0, l0);
        split2(v.z, v.w, h1, l1);
        Xh32[2 * i]     = h0;  Xl32[2 * i]     = l0;
        Xh32[2 * i + 1] = h1;  Xl32[2 * i + 1] = l1;
    }

    uint32_t* Wh32 = (uint32_t*)g_Wh;
    uint32_t* Wl32 = (uint32_t*)g_Wl;
    for (int i = gid; i < 3 * CDIM * CDIM / 4; i += stride) {
        const int m = i / (CDIM * CDIM / 4);
        const int r = i % (CDIM * CDIM / 4);
        const float4* ws = (const float4*)((m == 0) ? wq : (m == 1) ? wk : wv);
        const float4 v = ws[r];
        uint32_t h0, l0, h1, l1;
        split2(v.x, v.y, h0, l0);
        split2(v.z, v.w, h1, l1);
        Wh32[2 * i]     = h0;  Wl32[2 * i]     = l0;
        Wh32[2 * i + 1] = h1;  Wl32[2 * i + 1] = l1;
    }
}

// ---------------------------------------------------------------------------
// Kernel 1: QKV projection via HMMA, 3-pass split (Xh*Wh + Xh*Wl + Xl*Wh).
// grid = 128 (row tiles of 128), block = 256 (8 warps x m16).
// smem: Xh @0 (32KB), Xl @32768, W double buffer @65536 (each 64KB: Wh+Wl).
// ---------------------------------------------------------------------------
#define SM_PROJ_W 65536
#define SMEM_PROJ_BYTES (65536 + 2 * 65536)

__global__ void __launch_bounds__(256, 1) qkv_proj_kernel(
    const float* __restrict__ bq, const float* __restrict__ bk,
    const float* __restrict__ bv)
{
    extern __shared__ __align__(1024) char smem[];
    const uint32_t sbase = smem_u32(smem);

    const int tid  = threadIdx.x;
    const int lane = tid & 31;
    const int wrp  = tid >> 5;
    const int m0   = wrp * 16;
    const int r0   = blockIdx.x * 128;

    const uint64_t gXh = gaddr(g_Xh) + (size_t)r0 * CDIM * 2;
    const uint64_t gXl = gaddr(g_Xl) + (size_t)r0 * CDIM * 2;
    const uint64_t gWh = gaddr(g_Wh);
    const uint64_t gWl = gaddr(g_Wl);

    // Stage X (hi+lo) + W0 into buffer 0.
    #pragma unroll
    for (int i = 0; i < 16; i++) {
        int idx = tid + i * 256;               // 0..4095
        int arr = idx >> 11;                   // 0=hi 1=lo
        int rem = idx & 2047;
        int r   = rem >> 4;
        int c   = rem & 15;
        uint32_t dst = sbase + arr * 32768 + r * 256 + ((c ^ (r & 7)) << 4);
        CP16(dst, (arr ? gXl : gXh) + ((size_t)r * CDIM + c * 8) * 2);
    }
    #pragma unroll
    for (int i = 0; i < 16; i++) {
        int idx = tid + i * 256;
        int arr = idx >> 11;
        int rem = idx & 2047;
        int r   = rem >> 4;
        int c   = rem & 15;
        uint32_t dst = sbase + SM_PROJ_W + arr * 32768 + r * 256
                     + ((c ^ (r & 7)) << 4);
        CP16(dst, (arr ? gWl : gWh) + ((size_t)r * CDIM + c * 8) * 2);
    }
    CP_COMMIT();

    const int ln7  = lane & 7;
    const int selA = (lane >> 3) & 1;
    const int selB = (lane >> 4) & 1;

    const int xrow = m0 + ln7 + selA * 8;
    const uint32_t xbh = sbase + xrow * 256;
    const int xswz = xrow & 7;

    for (int m = 0; m < 3; m++) {
        if (m > 0) __syncthreads();           // all warps done with prev buffer
        if (m < 2) {
            const uint32_t wbuf = sbase + SM_PROJ_W + ((m + 1) & 1) * 65536;
            #pragma unroll
            for (int i = 0; i < 16; i++) {
                int idx = tid + i * 256;
                int arr = idx >> 11;
                int rem = idx & 2047;
                int r   = rem >> 4;
                int c   = rem & 15;
                uint32_t dst = wbuf + arr * 32768 + r * 256
                             + ((c ^ (r & 7)) << 4);
                const size_t off = ((size_t)(m + 1) * CDIM * CDIM
                                  + (size_t)r * CDIM + c * 8) * 2;
                CP16(dst, (arr ? gWl : gWh) + off);
            }
            CP_COMMIT();
            CP_WAIT1();
        } else {
            CP_WAIT0();
        }
        __syncthreads();

        const uint32_t wb = sbase + SM_PROJ_W + (m & 1) * 65536;

        float O[16][4];
        #pragma unroll
        for (int t = 0; t < 16; t++)
            #pragma unroll
            for (int j = 0; j < 4; j++) O[t][j] = 0.0f;

        #pragma unroll
        for (int ks = 0; ks < 8; ks++) {
            const int xc = 2 * ks + selB;
            const uint32_t xa = xbh + ((xc ^ xswz) << 4);
            uint32_t xh[4], xl[4];
            LDSM_X4(xh, xa);
            LDSM_X4(xl, xa + 32768);

            const int wrow = ks * 16 + selA * 8 + ln7;
            const uint32_t wbr = wb + wrow * 256;
            const int wswz = wrow & 7;

            #pragma unroll
            for (int dp = 0; dp < 8; dp++) {
                const int wc = 2 * dp + selB;
                const uint32_t wa = wbr + ((wc ^ wswz) << 4);
                uint32_t wh[4], wl[4];
                LDSM_X4T(wh, wa);
                LDSM_X4T(wl, wa + 32768);
                MMA16816(O[2 * dp],     xh, wh[0], wh[1]);
                MMA16816(O[2 * dp],     xh, wl[0], wl[1]);
                MMA16816(O[2 * dp],     xl, wh[0], wh[1]);
                MMA16816(O[2 * dp + 1], xh, wh[2], wh[3]);
                MMA16816(O[2 * dp + 1], xh, wl[2], wl[3]);
                MMA16816(O[2 * dp + 1], xl, wh[2], wh[3]);
            }
        }

        // Epilogue: bias + store (Q: split hi/lo; K,V: fp16 rn)
        const float* bias = (m == 0) ? bq : ((m == 1) ? bk : bv);
        const int gr0 = r0 + m0 + (lane >> 2);
        #pragma unroll
        for (int t = 0; t < 16; t++) {
            const int c0 = (t >> 1) * 16 + (t & 1) * 8 + 2 * (lane & 3);
            const float b0 = bias[c0];
            const float b1 = bias[c0 + 1];
            const float y00 = O[t][0] + b0, y01 = O[t][1] + b1;
            const float y10 = O[t][2] + b0, y11 = O[t][3] + b1;
            if (m == 0) {
                uint32_t h, l;
                split2(y00, y01, h, l);
                *(uint32_t*)(g_Qh + (size_t)gr0 * CDIM + c0) = h;
                *(uint32_t*)(g_Ql + (size_t)gr0 * CDIM + c0) = l;
                split2(y10, y11, h, l);
                *(uint32_t*)(g_Qh + (size_t)(gr0 + 8) * CDIM + c0) = h;
                *(uint32_t*)(g_Ql + (size_t)(gr0 + 8) * CDIM + c0) = l;
            } else {
                __half* dst = (m == 1) ? g_Kh : g_Vh;
                *(uint32_t*)(dst + (size_t)gr0 * CDIM + c0)       = pack2(y00, y01);
                *(uint32_t*)(dst + (size_t)(gr0 + 8) * CDIM + c0) = pack2(y10, y11);
            }
        }
    }
}

// ---------------------------------------------------------------------------
// Kernel 2: HMMA flash attention.
//   S = (Qh+Ql) * Kh   (2-pass),   O = Ph * Vh   (1-pass; P error averages
//   across keys and l is accumulated in fp32 pre-rounding)
// grid = (N/BM, B), block = 256 (8 warps x m16). No-max softmax (exp2).
// smem: Qh @0 (32KB), Ql @32768, KV dbuf @65536 (each 32KB: Kh+Vh).
// ---------------------------------------------------------------------------
#define SM_KV  65536
#define SMEM_ATTN_BYTES (65536 + 2 * 32768)

__global__ void __launch_bounds__(256, 1) attn_kernel(float* __restrict__ out)
{
    extern __shared__ __align__(1024) char smem[];
    const uint32_t sbase = smem_u32(smem);

    const int b    = blockIdx.y;
    const int q0   = blockIdx.x * BM;
    const int tid  = threadIdx.x;
    const int lane = tid & 31;
    const int wrp  = tid >> 5;
    const int m0   = wrp * 16;

    const uint64_t gQh = gaddr(g_Qh) + ((size_t)(b * NSEQ + q0) * CDIM) * 2;
    const uint64_t gQl = gaddr(g_Ql) + ((size_t)(b * NSEQ + q0) * CDIM) * 2;
    const uint64_t gKh = gaddr(g_Kh) + ((size_t)(b * NSEQ) * CDIM) * 2;
    const uint64_t gVh = gaddr(g_Vh) + ((size_t)(b * NSEQ) * CDIM) * 2;

    // ---- stage Q hi+lo (once) ----
    #pragma unroll
    for (int i = 0; i < 16; i++) {
        int idx = tid + i * 256;               // 0..4095
        int arr = idx >> 11;
        int rem = idx & 2047;
        int r   = rem >> 4;
        int c   = rem & 15;
        uint32_t dst = sbase + arr * 32768 + r * 256 + ((c ^ (r & 7)) << 4);
        CP16(dst, (arr ? gQl : gQh) + ((size_t)r * CDIM + c * 8) * 2);
    }
    // ---- stage KV tile 0 ----
    #pragma unroll
    for (int i = 0; i < 8; i++) {
        int idx = tid + i * 256;               // 0..2047
        int arr = idx >> 10;                   // 0=Kh 1=Vh
        int rem = idx & 1023;
        int r   = rem >> 4;
        int c   = rem & 15;
        uint32_t dst = sbase + SM_KV + arr * 16384 + r * 256
                     + ((c ^ (r & 7)) << 4);
        CP16(dst, (arr ? gVh : gKh) + ((size_t)r * CDIM + c * 8) * 2);
    }
    CP_COMMIT();
    CP_WAIT0();
    __syncthreads();

    const int ln7  = lane & 7;
    const int selA = (lane >> 3) & 1;
    const int selB = (lane >> 4) & 1;

    const int qrow = m0 + ln7 + selA * 8;
    const uint32_t qbh = sbase + qrow * 256;
    const int qswz = qrow & 7;

    // ---- hoist Q-hi fragments into registers for the whole loop ----
    uint32_t qh[8][4];
    #pragma unroll
    for (int ks = 0; ks < 8; ks++) {
        const uint32_t qa = qbh + (((2 * ks + selB) ^ qswz) << 4);
        LDSM_X4(qh[ks], qa);
    }

    float O[16][4];
    #pragma unroll
    for (int t = 0; t < 16; t++)
        #pragma unroll
        for (int j = 0; j < 4; j++) O[t][j] = 0.0f;
    float l0 = 0.0f, l1 = 0.0f;

    for (int kt = 0; kt < NKT; kt++) {
        const int s = kt & 1;
        const uint32_t kvb = sbase + SM_KV + s * 32768;

        if (kt + 1 < NKT) {
            const uint32_t kvn = sbase + SM_KV + (s ^ 1) * 32768;
            const size_t rowoff = (size_t)(kt + 1) * BN;
            #pragma unroll
            for (int i = 0; i < 8; i++) {
                int idx = tid + i * 256;
                int arr = idx >> 10;
                int rem = idx & 1023;
                int r   = rem >> 4;
                int c   = rem & 15;
                uint32_t dst = kvn + arr * 16384 + r * 256 + ((c ^ (r & 7)) << 4);
                CP16(dst, (arr ? gVh : gKh) + ((rowoff + r) * CDIM + c * 8) * 2);
            }
            CP_COMMIT();
            CP_WAIT1();
        } else {
            CP_WAIT0();
        }
        __syncthreads();

        // ================= S = Q K^T : (qh + ql) * kh =================
        float S[8][4];
        #pragma unroll
        for (int t = 0; t < 8; t++)
            #pragma unroll
            for (int j = 0; j < 4; j++) S[t][j] = 0.0f;

        #pragma unroll
        for (int ks = 0; ks < 8; ks++) {
            const uint32_t qa = qbh + (((2 * ks + selB) ^ qswz) << 4);
            uint32_t ql[4];
            LDSM_X4(ql, qa + 32768);

            #pragma unroll
            for (int p = 0; p < 4; p++) {
                const int kr = p * 16 + selB * 8 + ln7;
                const int kc = 2 * ks + selA;
                const uint32_t ka = kvb + kr * 256 + ((kc ^ (kr & 7)) << 4);
                uint32_t kh[4];
                LDSM_X4(kh, ka);
                MMA16816(S[2 * p],     qh[ks], kh[0], kh[1]);
                MMA16816(S[2 * p],     ql,     kh[0], kh[1]);
                MMA16816(S[2 * p + 1], qh[ks], kh[2], kh[3]);
                MMA16816(S[2 * p + 1], ql,     kh[2], kh[3]);
            }
        }

        // ================= softmax (no max, exp2 w/ folded scale) ========
        #pragma unroll
        for (int t = 0; t < 8; t++) {
            #pragma unroll
            for (int j = 0; j < 4; j++) {
                const float p = exp2f(S[t][j] * EXP2_SCALE);
                S[t][j] = p;
                if (j < 2) l0 += p; else l1 += p;
            }
        }

        // ================= O += P V : ph * vh (1-pass) =================
        #pragma unroll
        for (int kv = 0; kv < 4; kv++) {
            uint32_t ah[4];
            ah[0] = pack2(S[2 * kv][0],     S[2 * kv][1]);
            ah[1] = pack2(S[2 * kv][2],     S[2 * kv][3]);
            ah[2] = pack2(S[2 * kv + 1][0], S[2 * kv + 1][1]);
            ah[3] = pack2(S[2 * kv + 1][2], S[2 * kv + 1][3]);

            const int vrow = kv * 16 + selA * 8 + ln7;
            const uint32_t vb = kvb + 16384 + vrow * 256;
            const int vswz = vrow & 7;

            #pragma unroll
            for (int dp = 0; dp < 8; dp++) {
                const int vc = 2 * dp + selB;
                const uint32_t va = vb + ((vc ^ vswz) << 4);
                uint32_t vh[4];
                LDSM_X4T(vh, va);
                MMA16816(O[2 * dp],     ah, vh[0], vh[1]);
                MMA16816(O[2 * dp + 1], ah, vh[2], vh[3]);
            }
        }
        __syncthreads();
    }

    // ================= epilogue =================
    l0 += __shfl_xor_sync(0xffffffffu, l0, 1);
    l0 += __shfl_xor_sync(0xffffffffu, l0, 2);
    l1 += __shfl_xor_sync(0xffffffffu, l1, 1);
    l1 += __shfl_xor_sync(0xffffffffu, l1, 2);
    const float inv0 = 1.0f / l0;
    const float inv1 = 1.0f / l1;

    const int grow = b * NSEQ + q0 + m0 + (lane >> 2);
    float* o0 = out + (size_t)grow * CDIM;
    float* o1 = o0 + 8 * CDIM;
    const int cb = (lane & 3) * 2;

    #pragma unroll
    for (int t = 0; t < 16; t++) {
        float2 r0v, r1v;
        r0v.x = O[t][0] * inv0;  r0v.y = O[t][1] * inv0;
        r1v.x = O[t][2] * inv1;  r1v.y = O[t][3] * inv1;
        *(float2*)(o0 + t * 8 + cb) = r0v;
        *(float2*)(o1 + t * 8 + cb) = r1v;
    }
}

// ---------------------------------------------------------------------------
// Launch
// ---------------------------------------------------------------------------
extern "C" void kernel_launch(void* const* d_in, const int* in_sizes, int n_in,
                              void* d_out, int out_size)
{
    const float* x  = (const float*)d_in[0];
    const float* wq = (const float*)d_in[1];
    const float* bq = (const float*)d_in[2];
    const float* wk = (const float*)d_in[3];
    const float* bk = (const float*)d_in[4];
    const float* wv = (const float*)d_in[5];
    const float* bv = (const float*)d_in[6];
    float* out = (float*)d_out;

    conv_kernel<<<1024, 256>>>(x, wq, wk, wv);

    cudaFuncSetAttribute(qkv_proj_kernel,
                         cudaFuncAttributeMaxDynamicSharedMemorySize,
                         SMEM_PROJ_BYTES);
    qkv_proj_kernel<<<BATCH * NSEQ / 128, 256, SMEM_PROJ_BYTES>>>(bq, bk, bv);

    cudaFuncSetAttribute(attn_kernel,
                         cudaFuncAttributeMaxDynamicSharedMemorySize,
                         SMEM_ATTN_BYTES);
    dim3 g2(NSEQ / BM, BATCH);
    attn_kernel<<<g2, 256, SMEM_ATTN_BYTES>>>(out);
}

// round 8
// speedup vs baseline: 9.9368x; 1.3832x over previous
#include <cuda_runtime.h>
#include <cuda_fp16.h>
#include <cstdint>
#include <math.h>

#define BATCH 4
#define NSEQ  4096
#define CDIM  128
#define BM    128
#define BN    64
#define NKT   (NSEQ / BN)                  // 64 key tiles
// 1/sqrt(128) * log2(e)  (fold softmax scale into exp2)
#define EXP2_SCALE 0.12752465736070462f

// ---------------------------------------------------------------------------
// Global scratch (device globals: allocation-free).
// ---------------------------------------------------------------------------
__device__ __half g_Xh[BATCH * NSEQ * CDIM];   // x split hi
__device__ __half g_Xl[BATCH * NSEQ * CDIM];   // x split lo
__device__ __half g_Wh[3 * CDIM * CDIM];       // wq,wk,wv rounded fp16
__device__ __half g_Qh[BATCH * NSEQ * CDIM];   // Q rounded fp16
__device__ __half g_Kh[BATCH * NSEQ * CDIM];   // K rounded fp16
__device__ __half g_Vh[BATCH * NSEQ * CDIM];   // V rounded fp16

// ---------------------------------------------------------------------------
// PTX helpers (sm_80-baseline features only)
// ---------------------------------------------------------------------------
__device__ __forceinline__ uint32_t smem_u32(const void* p) {
    uint32_t a;
    asm("{ .reg .u64 t; cvta.to.shared.u64 t, %1; cvt.u32.u64 %0, t; }"
        : "=r"(a) : "l"(p));
    return a;
}
__device__ __forceinline__ uint64_t gaddr(const void* p) {
    uint64_t r;
    asm("cvta.to.global.u64 %0, %1;" : "=l"(r) : "l"(p));
    return r;
}

#define LDSM_X4(R, a) \
    asm volatile("ldmatrix.sync.aligned.m8n8.x4.shared.b16 {%0,%1,%2,%3}, [%4];" \
        : "=r"((R)[0]), "=r"((R)[1]), "=r"((R)[2]), "=r"((R)[3]) : "r"(a))
#define LDSM_X4T(R, a) \
    asm volatile("ldmatrix.sync.aligned.m8n8.x4.trans.shared.b16 {%0,%1,%2,%3}, [%4];" \
        : "=r"((R)[0]), "=r"((R)[1]), "=r"((R)[2]), "=r"((R)[3]) : "r"(a))

#define MMA16816(D, A, B0, B1) \
    asm volatile("mma.sync.aligned.m16n8k16.row.col.f32.f16.f16.f32 " \
        "{%0,%1,%2,%3}, {%4,%5,%6,%7}, {%8,%9}, {%0,%1,%2,%3};" \
        : "+f"((D)[0]), "+f"((D)[1]), "+f"((D)[2]), "+f"((D)[3]) \
        : "r"((A)[0]), "r"((A)[1]), "r"((A)[2]), "r"((A)[3]), "r"(B0), "r"(B1))

#define CP16(dst, src) \
    asm volatile("cp.async.cg.shared.global [%0], [%1], 16;" \
        :: "r"(dst), "l"(src) : "memory")
#define CP_COMMIT() asm volatile("cp.async.commit_group;" ::: "memory")
#define CP_WAIT1()  asm volatile("cp.async.wait_group 1;" ::: "memory")
#define CP_WAIT0()  asm volatile("cp.async.wait_group 0;" ::: "memory")

// Split fp32 pair -> packed fp16 hi / fp16 lo
__device__ __forceinline__ void split2(float x, float y,
                                       uint32_t& hi, uint32_t& lo) {
    __half hx = __float2half_rn(x), hy = __float2half_rn(y);
    __half2 h2 = __halves2half2(hx, hy);
    __half2 l2 = __floats2half2_rn(x - __half2float(hx), y - __half2float(hy));
    hi = *(uint32_t*)&h2;
    lo = *(uint32_t*)&l2;
}
// Round fp32 pair -> packed fp16
__device__ __forceinline__ uint32_t pack2(float x, float y) {
    __half2 h2 = __floats2half2_rn(x, y);
    return *(uint32_t*)&h2;
}

// ---------------------------------------------------------------------------
// Kernel 0: convert x (split hi/lo) and weights (rounded) to fp16.
// ---------------------------------------------------------------------------
__global__ void __launch_bounds__(256) conv_kernel(
    const float* __restrict__ x,
    const float* __restrict__ wq, const float* __restrict__ wk,
    const float* __restrict__ wv)
{
    const int gid    = blockIdx.x * blockDim.x + threadIdx.x;
    const int stride = gridDim.x * blockDim.x;

    uint32_t* Xh32 = (uint32_t*)g_Xh;
    uint32_t* Xl32 = (uint32_t*)g_Xl;
    const float4* x4 = (const float4*)x;
    for (int i = gid; i < BATCH * NSEQ * CDIM / 4; i += stride) {
        const float4 v = x4[i];
        uint32_t h0, l0, h1, l1;
        split2(v.x, v.y, h0, l0);
        split2(v.z, v.w, h1, l1);
        Xh32[2 * i]     = h0;  Xl32[2 * i]     = l0;
        Xh32[2 * i + 1] = h1;  Xl32[2 * i + 1] = l1;
    }

    uint32_t* Wh32 = (uint32_t*)g_Wh;
    for (int i = gid; i < 3 * CDIM * CDIM / 4; i += stride) {
        const int m = i / (CDIM * CDIM / 4);
        const int r = i % (CDIM * CDIM / 4);
        const float4* ws = (const float4*)((m == 0) ? wq : (m == 1) ? wk : wv);
        const float4 v = ws[r];
        Wh32[2 * i]     = pack2(v.x, v.y);
        Wh32[2 * i + 1] = pack2(v.z, v.w);
    }
}

// ---------------------------------------------------------------------------
// Kernel 1: QKV projection via HMMA, 2-pass split ((Xh + Xl) * Wh).
// grid = 128 (row tiles of 128), block = 256 (8 warps x m16).
// smem: Xh @0 (32KB), Xl @32768, Wh double buffer @65536 (each 32KB).
// ---------------------------------------------------------------------------
#define SM_PROJ_W 65536
#define SMEM_PROJ_BYTES (65536 + 2 * 32768)

__global__ void __launch_bounds__(256, 1) qkv_proj_kernel(
    const float* __restrict__ bq, const float* __restrict__ bk,
    const float* __restrict__ bv)
{
    extern __shared__ __align__(1024) char smem[];
    const uint32_t sbase = smem_u32(smem);

    const int tid  = threadIdx.x;
    const int lane = tid & 31;
    const int wrp  = tid >> 5;
    const int m0   = wrp * 16;
    const int r0   = blockIdx.x * 128;

    const uint64_t gXh = gaddr(g_Xh) + (size_t)r0 * CDIM * 2;
    const uint64_t gXl = gaddr(g_Xl) + (size_t)r0 * CDIM * 2;
    const uint64_t gWh = gaddr(g_Wh);

    // Stage X (hi+lo) + W0 into buffer 0.
    #pragma unroll
    for (int i = 0; i < 16; i++) {
        int idx = tid + i * 256;               // 0..4095
        int arr = idx >> 11;                   // 0=hi 1=lo
        int rem = idx & 2047;
        int r   = rem >> 4;
        int c   = rem & 15;
        uint32_t dst = sbase + arr * 32768 + r * 256 + ((c ^ (r & 7)) << 4);
        CP16(dst, (arr ? gXl : gXh) + ((size_t)r * CDIM + c * 8) * 2);
    }
    #pragma unroll
    for (int i = 0; i < 8; i++) {
        int idx = tid + i * 256;               // 0..2047
        int r   = idx >> 4;
        int c   = idx & 15;
        uint32_t dst = sbase + SM_PROJ_W + r * 256 + ((c ^ (r & 7)) << 4);
        CP16(dst, gWh + ((size_t)r * CDIM + c * 8) * 2);
    }
    CP_COMMIT();

    const int ln7  = lane & 7;
    const int selA = (lane >> 3) & 1;
    const int selB = (lane >> 4) & 1;

    const int xrow = m0 + ln7 + selA * 8;
    const uint32_t xbh = sbase + xrow * 256;
    const int xswz = xrow & 7;

    for (int m = 0; m < 3; m++) {
        if (m > 0) __syncthreads();           // all warps done with prev buffer
        if (m < 2) {
            const uint32_t wbuf = sbase + SM_PROJ_W + ((m + 1) & 1) * 32768;
            #pragma unroll
            for (int i = 0; i < 8; i++) {
                int idx = tid + i * 256;
                int r   = idx >> 4;
                int c   = idx & 15;
                uint32_t dst = wbuf + r * 256 + ((c ^ (r & 7)) << 4);
                const size_t off = ((size_t)(m + 1) * CDIM * CDIM
                                  + (size_t)r * CDIM + c * 8) * 2;
                CP16(dst, gWh + off);
            }
            CP_COMMIT();
            CP_WAIT1();
        } else {
            CP_WAIT0();
        }
        __syncthreads();

        const uint32_t wb = sbase + SM_PROJ_W + (m & 1) * 32768;

        float O[16][4];
        #pragma unroll
        for (int t = 0; t < 16; t++)
            #pragma unroll
            for (int j = 0; j < 4; j++) O[t][j] = 0.0f;

        #pragma unroll
        for (int ks = 0; ks < 8; ks++) {
            const int xc = 2 * ks + selB;
            const uint32_t xa = xbh + ((xc ^ xswz) << 4);
            uint32_t xh[4], xl[4];
            LDSM_X4(xh, xa);
            LDSM_X4(xl, xa + 32768);

            const int wrow = ks * 16 + selA * 8 + ln7;
            const uint32_t wbr = wb + wrow * 256;
            const int wswz = wrow & 7;

            #pragma unroll
            for (int dp = 0; dp < 8; dp++) {
                const int wc = 2 * dp + selB;
                const uint32_t wa = wbr + ((wc ^ wswz) << 4);
                uint32_t wh[4];
                LDSM_X4T(wh, wa);
                MMA16816(O[2 * dp],     xh, wh[0], wh[1]);
                MMA16816(O[2 * dp],     xl, wh[0], wh[1]);
                MMA16816(O[2 * dp + 1], xh, wh[2], wh[3]);
                MMA16816(O[2 * dp + 1], xl, wh[2], wh[3]);
            }
        }

        // Epilogue: bias + round to fp16.
        const float* bias = (m == 0) ? bq : ((m == 1) ? bk : bv);
        __half* dst = (m == 0) ? g_Qh : ((m == 1) ? g_Kh : g_Vh);
        const int gr0 = r0 + m0 + (lane >> 2);
        #pragma unroll
        for (int t = 0; t < 16; t++) {
            const int c0 = (t >> 1) * 16 + (t & 1) * 8 + 2 * (lane & 3);
            const float b0 = bias[c0];
            const float b1 = bias[c0 + 1];
            *(uint32_t*)(dst + (size_t)gr0 * CDIM + c0) =
                pack2(O[t][0] + b0, O[t][1] + b1);
            *(uint32_t*)(dst + (size_t)(gr0 + 8) * CDIM + c0) =
                pack2(O[t][2] + b0, O[t][3] + b1);
        }
    }
}

// ---------------------------------------------------------------------------
// Kernel 2: HMMA flash attention, all-fp16 operands (1-pass QK, 1-pass PV).
// grid = (N/BM, B), block = 256 (8 warps x m16). No-max softmax (exp2).
// smem: Qh @0 (32KB), KV dbuf @32768 (each 32KB: Kh+Vh).
// ---------------------------------------------------------------------------
#define SM_KV  32768
#define SMEM_ATTN_BYTES (32768 + 2 * 32768)

__global__ void __launch_bounds__(256, 1) attn_kernel(float* __restrict__ out)
{
    extern __shared__ __align__(1024) char smem[];
    const uint32_t sbase = smem_u32(smem);

    const int b    = blockIdx.y;
    const int q0   = blockIdx.x * BM;
    const int tid  = threadIdx.x;
    const int lane = tid & 31;
    const int wrp  = tid >> 5;
    const int m0   = wrp * 16;

    const uint64_t gQh = gaddr(g_Qh) + ((size_t)(b * NSEQ + q0) * CDIM) * 2;
    const uint64_t gKh = gaddr(g_Kh) + ((size_t)(b * NSEQ) * CDIM) * 2;
    const uint64_t gVh = gaddr(g_Vh) + ((size_t)(b * NSEQ) * CDIM) * 2;

    // ---- stage Q (once) ----
    #pragma unroll
    for (int i = 0; i < 8; i++) {
        int idx = tid + i * 256;               // 0..2047
        int r   = idx >> 4;
        int c   = idx & 15;
        uint32_t dst = sbase + r * 256 + ((c ^ (r & 7)) << 4);
        CP16(dst, gQh + ((size_t)r * CDIM + c * 8) * 2);
    }
    // ---- stage KV tile 0 ----
    #pragma unroll
    for (int i = 0; i < 8; i++) {
        int idx = tid + i * 256;               // 0..2047
        int arr = idx >> 10;                   // 0=Kh 1=Vh
        int rem = idx & 1023;
        int r   = rem >> 4;
        int c   = rem & 15;
        uint32_t dst = sbase + SM_KV + arr * 16384 + r * 256
                     + ((c ^ (r & 7)) << 4);
        CP16(dst, (arr ? gVh : gKh) + ((size_t)r * CDIM + c * 8) * 2);
    }
    CP_COMMIT();
    CP_WAIT0();
    __syncthreads();

    const int ln7  = lane & 7;
    const int selA = (lane >> 3) & 1;
    const int selB = (lane >> 4) & 1;

    const int qrow = m0 + ln7 + selA * 8;
    const uint32_t qbh = sbase + qrow * 256;
    const int qswz = qrow & 7;

    // ---- hoist Q fragments into registers for the whole loop ----
    uint32_t qh[8][4];
    #pragma unroll
    for (int ks = 0; ks < 8; ks++) {
        const uint32_t qa = qbh + (((2 * ks + selB) ^ qswz) << 4);
        LDSM_X4(qh[ks], qa);
    }

    float O[16][4];
    #pragma unroll
    for (int t = 0; t < 16; t++)
        #pragma unroll
        for (int j = 0; j < 4; j++) O[t][j] = 0.0f;
    float l0 = 0.0f, l1 = 0.0f;

    for (int kt = 0; kt < NKT; kt++) {
        const int s = kt & 1;
        const uint32_t kvb = sbase + SM_KV + s * 32768;

        if (kt + 1 < NKT) {
            const uint32_t kvn = sbase + SM_KV + (s ^ 1) * 32768;
            const size_t rowoff = (size_t)(kt + 1) * BN;
            #pragma unroll
            for (int i = 0; i < 8; i++) {
                int idx = tid + i * 256;
                int arr = idx >> 10;
                int rem = idx & 1023;
                int r   = rem >> 4;
                int c   = rem & 15;
                uint32_t dst = kvn + arr * 16384 + r * 256 + ((c ^ (r & 7)) << 4);
                CP16(dst, (arr ? gVh : gKh) + ((rowoff + r) * CDIM + c * 8) * 2);
            }
            CP_COMMIT();
            CP_WAIT1();
        } else {
            CP_WAIT0();
        }
        __syncthreads();

        // ================= S = Q K^T : qh * kh (1-pass) =================
        float S[8][4];
        #pragma unroll
        for (int t = 0; t < 8; t++)
            #pragma unroll
            for (int j = 0; j < 4; j++) S[t][j] = 0.0f;

        #pragma unroll
        for (int ks = 0; ks < 8; ks++) {
            #pragma unroll
            for (int p = 0; p < 4; p++) {
                const int kr = p * 16 + selB * 8 + ln7;
                const int kc = 2 * ks + selA;
                const uint32_t ka = kvb + kr * 256 + ((kc ^ (kr & 7)) << 4);
                uint32_t kh[4];
                LDSM_X4(kh, ka);
                MMA16816(S[2 * p],     qh[ks], kh[0], kh[1]);
                MMA16816(S[2 * p + 1], qh[ks], kh[2], kh[3]);
            }
        }

        // ================= softmax (no max, exp2 w/ folded scale) ========
        #pragma unroll
        for (int t = 0; t < 8; t++) {
            #pragma unroll
            for (int j = 0; j < 4; j++) {
                const float p = exp2f(S[t][j] * EXP2_SCALE);
                S[t][j] = p;
                if (j < 2) l0 += p; else l1 += p;
            }
        }

        // ================= O += P V : ph * vh (1-pass) =================
        #pragma unroll
        for (int kv = 0; kv < 4; kv++) {
            uint32_t ah[4];
            ah[0] = pack2(S[2 * kv][0],     S[2 * kv][1]);
            ah[1] = pack2(S[2 * kv][2],     S[2 * kv][3]);
            ah[2] = pack2(S[2 * kv + 1][0], S[2 * kv + 1][1]);
            ah[3] = pack2(S[2 * kv + 1][2], S[2 * kv + 1][3]);

            const int vrow = kv * 16 + selA * 8 + ln7;
            const uint32_t vb = kvb + 16384 + vrow * 256;
            const int vswz = vrow & 7;

            #pragma unroll
            for (int dp = 0; dp < 8; dp++) {
                const int vc = 2 * dp + selB;
                const uint32_t va = vb + ((vc ^ vswz) << 4);
                uint32_t vh[4];
                LDSM_X4T(vh, va);
                MMA16816(O[2 * dp],     ah, vh[0], vh[1]);
                MMA16816(O[2 * dp + 1], ah, vh[2], vh[3]);
            }
        }
        __syncthreads();
    }

    // ================= epilogue =================
    l0 += __shfl_xor_sync(0xffffffffu, l0, 1);
    l0 += __shfl_xor_sync(0xffffffffu, l0, 2);
    l1 += __shfl_xor_sync(0xffffffffu, l1, 1);
    l1 += __shfl_xor_sync(0xffffffffu, l1, 2);
    const float inv0 = 1.0f / l0;
    const float inv1 = 1.0f / l1;

    const int grow = b * NSEQ + q0 + m0 + (lane >> 2);
    float* o0 = out + (size_t)grow * CDIM;
    float* o1 = o0 + 8 * CDIM;
    const int cb = (lane & 3) * 2;

    #pragma unroll
    for (int t = 0; t < 16; t++) {
        float2 r0v, r1v;
        r0v.x = O[t][0] * inv0;  r0v.y = O[t][1] * inv0;
        r1v.x = O[t][2] * inv1;  r1v.y = O[t][3] * inv1;
        *(float2*)(o0 + t * 8 + cb) = r0v;
        *(float2*)(o1 + t * 8 + cb) = r1v;
    }
}

// ---------------------------------------------------------------------------
// Launch
// ---------------------------------------------------------------------------
extern "C" void kernel_launch(void* const* d_in, const int* in_sizes, int n_in,
                              void* d_out, int out_size)
{
    const float* x  = (const float*)d_in[0];
    const float* wq = (const float*)d_in[1];
    const float* bq = (const float*)d_in[2];
    const float* wk = (const float*)d_in[3];
    const float* bk = (const float*)d_in[4];
    const float* wv = (const float*)d_in[5];
    const float* bv = (const float*)d_in[6];
    float* out = (float*)d_out;

    conv_kernel<<<1024, 256>>>(x, wq, wk, wv);

    cudaFuncSetAttribute(qkv_proj_kernel,
                         cudaFuncAttributeMaxDynamicSharedMemorySize,
                         SMEM_PROJ_BYTES);
    qkv_proj_kernel<<<BATCH * NSEQ / 128, 256, SMEM_PROJ_BYTES>>>(bq, bk, bv);

    cudaFuncSetAttribute(attn_kernel,
                         cudaFuncAttributeMaxDynamicSharedMemorySize,
                         SMEM_ATTN_BYTES);
    dim3 g2(NSEQ / BM, BATCH);
    attn_kernel<<<g2, 256, SMEM_ATTN_BYTES>>>(out);
}